// round 12
// baseline (speedup 1.0000x reference)
#include <cuda_runtime.h>

// -------------------------------------------------------------------------
// MaskedBilinearFullSymLoss — B=16, C=2, H=W=512, scalar f32 output.
// Persistent single-wave kernel (1036 blocks = 7/SM x 148) with atomic work
// stealing over 2048 units (unit = one batch b x 4-row strip). Body:
// float2 loads, parity-templated shifted windows, 4-row sharing, 8 px/thr.
// -------------------------------------------------------------------------

#define HH 512
#define WW 512
#define NPERSIST 1036u

__device__ double g_acc;            // zero-initialized
__device__ unsigned int g_ticket;   // zero-initialized
__device__ unsigned int g_work;     // zero-initialized

__device__ __forceinline__ float2 ld2(const float* __restrict__ p) {
    return *(const float2*)p;
}

struct Ctx {
    const float* __restrict__ g0;
    const float* __restrict__ g1;
    const float* __restrict__ mk;
    float wx1, wx2, wy1, wy2, w11, w12, w21, w22, sym_x, sym_y;
    int dx1, dy1, dy2, imax, jmax, i0, j0;
};

// 3-float shifted window [ja, ja+1, ja+2]; P = ja parity. Clamped values are
// only consumed with a zero validity factor.
template<int P>
__device__ __forceinline__ void ldwin(const float* __restrict__ row, int ja,
                                      float& x0, float& x1, float& x2) {
    if (P == 0) {
        float2 v = ld2(row + min(ja, WW - 2));
        float  s = row[min(ja + 2, WW - 1)];
        x0 = v.x; x1 = v.y; x2 = s;
    } else {
        float2 a = ld2(row + min(ja - 1, WW - 2));
        float2 b = ld2(row + min(ja + 1, WW - 2));
        x0 = a.y; x1 = b.x; x2 = b.y;
    }
}

// 2-float window [c, c+1]; Q = c parity.
template<int Q>
__device__ __forceinline__ void ldpair(const float* __restrict__ row, int c,
                                       float& y0, float& y1) {
    if (Q == 0) {
        float2 v = ld2(row + min(c, WW - 2));
        y0 = v.x; y1 = v.y;
    } else {
        y0 = row[min(c,     WW - 1)];
        y1 = row[min(c + 1, WW - 1)];
    }
}

// ---- positive branch: output rows (ib, ib+1), cols (j0, j0+1)
template<int P>
__device__ __forceinline__ float pos_pair(const Ctx& c, int ib) {
    const int ja = c.j0 + c.dx1;
    int os[3];
    #pragma unroll
    for (int t = 0; t < 3; t++) os[t] = min(ib + c.dy1 + t, HH - 1) * WW;

    float X0[3], X1[3], X2[3];
    float Y0[3], Y1[3], Y2[3];
    #pragma unroll
    for (int t = 0; t < 3; t++) {
        ldwin<P>(c.g0 + os[t], ja, X0[t], X1[t], X2[t]);
        ldwin<P>(c.g1 + os[t], ja, Y0[t], Y1[t], Y2[t]);
    }

    const float jv0 = (c.j0     < c.jmax) ? 1.0f : 0.0f;
    const float jv1 = (c.j0 + 1 < c.jmax) ? 1.0f : 0.0f;

    float acc = 0.0f;
    #pragma unroll
    for (int r = 0; r < 2; r++) {
        const int oc = (ib + r) * WW + c.j0;     // always in-bounds
        float2 c0 = ld2(c.g0 + oc);
        float2 c1 = ld2(c.g1 + oc);
        float2 mm = ld2(c.mk + oc);
        const float rvv = (ib + r < c.imax) ? 1.0f : 0.0f;
        mm.x *= rvv * jv0;
        mm.y *= rvv * jv1;
        float s0 = c.w11 * X0[r] + c.w12 * X1[r] + c.w21 * X0[r+1] + c.w22 * X1[r+1];
        float s1 = c.w11 * Y0[r] + c.w12 * Y1[r] + c.w21 * Y0[r+1] + c.w22 * Y1[r+1];
        float e0 = (c0.x - s0) * c.sym_y + (c1.x - s1) * c.sym_x;
        acc += mm.x * e0 * e0;
        float t0 = c.w11 * X1[r] + c.w12 * X2[r] + c.w21 * X1[r+1] + c.w22 * X2[r+1];
        float t1 = c.w11 * Y1[r] + c.w12 * Y2[r] + c.w21 * Y1[r+1] + c.w22 * Y2[r+1];
        float e1 = (c0.y - t0) * c.sym_y + (c1.y - t1) * c.sym_x;
        acc += mm.y * e1 * e1;
    }
    return acc;
}

// ---- negative branch: rows (ib, ib+1), cols (j0, j0+1)
template<int Q>
__device__ __forceinline__ float neg_pair(const Ctx& c, int ib) {
    const int m2  = -c.dx1;            // >= 0
    const int cB0 = c.j0 + m2;

    float S0a[3], S0b[3], S1a[3], S1b[3];
    #pragma unroll
    for (int t = 0; t < 3; t++) {
        const int os = min(ib + t, HH - 1) * WW;
        ldpair<Q>(c.g0 + os, cB0, S0a[t], S0b[t]);
        ldpair<Q>(c.g1 + os, cB0, S1a[t], S1b[t]);
    }

    const float jv0 = (c.j0     < c.jmax) ? 1.0f : 0.0f;
    const float jv1 = (c.j0 + 1 < c.jmax) ? 1.0f : 0.0f;

    float acc = 0.0f;
    #pragma unroll
    for (int r = 0; r < 2; r++) {
        const int of = min(ib + c.dy2 + r, HH - 1) * WW;
        float2 v0 = ld2(c.g0 + of + c.j0);
        float2 v1 = ld2(c.g1 + of + c.j0);
        float z0 = c.g0[of + min(c.j0 + 2, WW - 1)];
        float z1 = c.g1[of + min(c.j0 + 2, WW - 1)];
        float mx, my;
        ldpair<Q>(c.mk + of, cB0, mx, my);
        const float rvv = (ib + r < c.imax) ? 1.0f : 0.0f;
        mx *= rvv * jv0;
        my *= rvv * jv1;
        float f0 = c.wx1 * v0.x + c.wx2 * v0.y;
        float f1 = c.wx1 * v1.x + c.wx2 * v1.y;
        float s0 = c.wy1 * S0a[r+1] + c.wy2 * S0a[r];
        float s1 = c.wy1 * S1a[r+1] + c.wy2 * S1a[r];
        float e0 = (f0 - s0) * c.sym_y + (f1 - s1) * c.sym_x;
        acc += mx * e0 * e0;
        float g0v = c.wx1 * v0.y + c.wx2 * z0;
        float g1v = c.wx1 * v1.y + c.wx2 * z1;
        float u0 = c.wy1 * S0b[r+1] + c.wy2 * S0b[r];
        float u1 = c.wy1 * S1b[r+1] + c.wy2 * S1b[r];
        float e1 = (g0v - u0) * c.sym_y + (g1v - u1) * c.sym_x;
        acc += my * e1 * e1;
    }
    return acc;
}

__global__ __launch_bounds__(256, 7)
void loss_kernel(const float* __restrict__ grid,
                 const float* __restrict__ gt,
                 const float* __restrict__ gd,
                 const float* __restrict__ mask,
                 int B, unsigned int units, float* __restrict__ out)
{
    const int H = HH, W = WW;
    const int tid = threadIdx.x;

    __shared__ unsigned int s_u;
    __shared__ float wsum[8];

    if (tid == 0) s_u = atomicAdd(&g_work, 1u);

    float facc = 0.0f;

    for (;;) {
        __syncthreads();
        const unsigned int u = s_u;
        __syncthreads();
        if (tid == 0) s_u = atomicAdd(&g_work, 1u);   // prefetch next unit
        if (u >= units) break;

        const int b  = (int)(u >> 7);         // 128 strips per batch item
        const int i0 = (int)(u & 127u) * 4;

        const float dx = -8.0f * gt[2 * b + 0];
        const float dy =  8.0f * gt[2 * b + 1];

        Ctx c;
        c.sym_x = gd[2 * b + 0];
        c.sym_y = gd[2 * b + 1];
        const float dx1f = floorf(dx), dy1f = floorf(dy);
        c.dx1 = (int)dx1f;  c.dy1 = (int)dy1f;  c.dy2 = c.dy1 + 1;
        const int dx2 = c.dx1 + 1;
        c.wx1 = (dx1f + 1.0f) - dx;  c.wx2 = dx - dx1f;
        c.wy1 = (dy1f + 1.0f) - dy;  c.wy2 = dy - dy1f;
        c.w11 = c.wy1 * c.wx1;  c.w12 = c.wy1 * c.wx2;
        c.w21 = c.wy2 * c.wx1;  c.w22 = c.wy2 * c.wx2;
        c.g0 = grid + (size_t)(2 * b + 0) * H * W;
        c.g1 = grid + (size_t)(2 * b + 1) * H * W;
        c.mk = mask + (size_t)b * H * W;
        c.imax = H - c.dy2;
        c.i0 = i0;
        c.j0 = 2 * tid;

        float uacc;
        float cnt;
        if (dx > 0.0f) {
            c.jmax = W - dx2;
            cnt = (float)c.imax * (float)c.jmax;
            if (c.dx1 & 1) uacc = pos_pair<1>(c, i0) + pos_pair<1>(c, i0 + 2);
            else           uacc = pos_pair<0>(c, i0) + pos_pair<0>(c, i0 + 2);
        } else {
            c.jmax = W + c.dx1;
            cnt = (float)c.imax * (float)c.jmax;
            if ((-c.dx1) & 1) uacc = neg_pair<1>(c, i0) + neg_pair<1>(c, i0 + 2);
            else              uacc = neg_pair<0>(c, i0) + neg_pair<0>(c, i0 + 2);
        }
        facc += __fdividef(uacc, cnt);
    }

    // ---- block reduction (8 warps)
    #pragma unroll
    for (int o = 16; o > 0; o >>= 1)
        facc += __shfl_down_sync(0xFFFFFFFFu, facc, o);

    const int lane = tid & 31;
    const int warp = tid >> 5;
    if (lane == 0) wsum[warp] = facc;
    __syncthreads();

    if (tid == 0) {
        float s = 0.0f;
        #pragma unroll
        for (int k = 0; k < 8; k++) s += wsum[k];
        atomicAdd(&g_acc, (double)s);

        __threadfence();
        unsigned int prev = atomicInc(&g_ticket, (unsigned int)gridDim.x - 1u);
        if (prev == (unsigned int)gridDim.x - 1u) {
            double total = atomicAdd(&g_acc, 0.0);    // atomic read
            out[0] = (float)(total / (double)B);
            g_acc  = 0.0;                             // reset for next replay
            g_work = 0u;
            __threadfence();
        }
    }
}

extern "C" void kernel_launch(void* const* d_in, const int* in_sizes, int n_in,
                              void* d_out, int out_size)
{
    const float* grid = (const float*)d_in[0];
    const float* gt   = (const float*)d_in[1];
    const float* gd   = (const float*)d_in[2];
    const float* mask = (const float*)d_in[3];
    float* out = (float*)d_out;

    const int B = in_sizes[1] / 2;            // gt_sym_axis is (B, 2)
    const unsigned int units = (unsigned int)(128 * B);

    loss_kernel<<<NPERSIST, 256>>>(grid, gt, gd, mask, B, units, out);
}

// round 13
// speedup vs baseline: 1.5951x; 1.5951x over previous
#include <cuda_runtime.h>

// -------------------------------------------------------------------------
// MaskedBilinearFullSymLoss — B=16, C=2, H=W=512, scalar f32 output.
// Persistent single-wave kernel (888 blocks = 6/SM x 148), work stealing
// over 2048 units (unit = batch b x 4-row strip).
// KEY: err is linear in channels => work on h = sym_y*g0 + sym_x*g1.
// Per unit, stage needed h-rows (5 pos / 9 neg) into shared memory with
// edge replication; shifted windows become LDS. LDG/unit/thread 36 -> ~22.
// -------------------------------------------------------------------------

#define HH 512
#define WW 512
#define ROWP 528            // padded smem row (512 + 16 replicated cols)
#define NPERSIST 888u

__device__ double g_acc;            // zero-initialized
__device__ unsigned int g_ticket;   // zero-initialized
__device__ unsigned int g_work;     // zero-initialized

__device__ __forceinline__ float2 ld2(const float* __restrict__ p) {
    return *(const float2*)p;
}

struct Prm {
    const float* __restrict__ g0;
    const float* __restrict__ g1;
    const float* __restrict__ mk;
    float wx1, wx2, wy1, wy2, w11, w12, w21, w22, sy, sx;
    int dx1, dy1, dy2, imax, jmax, i0, j0;
};

// 3-float window from padded smem row (no clamping needed; P = base parity)
template<int P>
__device__ __forceinline__ void swin(const float* row, int ja,
                                     float& x0, float& x1, float& x2) {
    if (P == 0) {
        float2 v = *(const float2*)(row + ja);
        x0 = v.x; x1 = v.y; x2 = row[ja + 2];
    } else {
        float2 a = *(const float2*)(row + ja - 1);
        float2 b = *(const float2*)(row + ja + 1);
        x0 = a.y; x1 = b.x; x2 = b.y;
    }
}

// 2-float window from padded smem row
template<int Q>
__device__ __forceinline__ void spair(const float* row, int c,
                                      float& y0, float& y1) {
    if (Q == 0) {
        float2 v = *(const float2*)(row + c);
        y0 = v.x; y1 = v.y;
    } else {
        y0 = row[c]; y1 = row[c + 1];
    }
}

// 2-float window from gmem row, clamped (clamped values consumed * 0)
template<int Q>
__device__ __forceinline__ void gpair(const float* __restrict__ row, int c,
                                      float& y0, float& y1) {
    if (Q == 0) {
        float2 v = ld2(row + min(c, WW - 2));
        y0 = v.x; y1 = v.y;
    } else {
        y0 = row[min(c, WW - 1)];
        y1 = row[min(c + 1, WW - 1)];
    }
}

// ---- positive branch: h staged in sh rows 0..4 (src rows i0+dy1+t)
template<int P>
__device__ __forceinline__ float pos_compute(const Prm& p, const float* sh) {
    const int ja = p.j0 + p.dx1;
    float X0[5], X1[5], X2[5];
    #pragma unroll
    for (int t = 0; t < 5; t++)
        swin<P>(sh + t * ROWP, ja, X0[t], X1[t], X2[t]);

    const float jv0 = (p.j0     < p.jmax) ? 1.0f : 0.0f;
    const float jv1 = (p.j0 + 1 < p.jmax) ? 1.0f : 0.0f;

    float acc = 0.0f;
    #pragma unroll
    for (int r = 0; r < 4; r++) {
        const int oc = (p.i0 + r) * WW + p.j0;     // always in-bounds
        float2 c0 = ld2(p.g0 + oc);
        float2 c1 = ld2(p.g1 + oc);
        float2 mm = ld2(p.mk + oc);
        const float rvv = (p.i0 + r < p.imax) ? 1.0f : 0.0f;
        mm.x *= rvv * jv0;
        mm.y *= rvv * jv1;
        float hcx = p.sy * c0.x + p.sx * c1.x;
        float hcy = p.sy * c0.y + p.sx * c1.y;
        float s0 = p.w11 * X0[r] + p.w12 * X1[r]
                 + p.w21 * X0[r+1] + p.w22 * X1[r+1];
        float e0 = hcx - s0;
        acc += mm.x * e0 * e0;
        float s1 = p.w11 * X1[r] + p.w12 * X2[r]
                 + p.w21 * X1[r+1] + p.w22 * X2[r+1];
        float e1 = hcy - s1;
        acc += mm.y * e1 * e1;
    }
    return acc;
}

// ---- negative branch: h staged rows 0..4 = src i0+t (second term),
//      rows 5..8 = src i0+dy2+t (first term)
template<int Q>
__device__ __forceinline__ float neg_compute(const Prm& p, const float* sh) {
    const int m2  = -p.dx1;            // >= 0
    const int cB0 = p.j0 + m2;

    float Sa[5], Sb[5];
    #pragma unroll
    for (int t = 0; t < 5; t++)
        spair<Q>(sh + t * ROWP, cB0, Sa[t], Sb[t]);

    const float jv0 = (p.j0     < p.jmax) ? 1.0f : 0.0f;
    const float jv1 = (p.j0 + 1 < p.jmax) ? 1.0f : 0.0f;

    float acc = 0.0f;
    #pragma unroll
    for (int r = 0; r < 4; r++) {
        const float* frow = sh + (5 + r) * ROWP;
        float2 hf = *(const float2*)(frow + p.j0);   // j0 even
        float  hf2 = frow[p.j0 + 2];                 // replication = col clamp
        float mx, my;
        const int of = min(p.i0 + p.dy2 + r, HH - 1) * WW;
        gpair<Q>(p.mk + of, cB0, mx, my);
        const float rvv = (p.i0 + r < p.imax) ? 1.0f : 0.0f;
        mx *= rvv * jv0;
        my *= rvv * jv1;
        float f0 = p.wx1 * hf.x + p.wx2 * hf.y;
        float s0 = p.wy1 * Sa[r+1] + p.wy2 * Sa[r];
        float e0 = f0 - s0;
        acc += mx * e0 * e0;
        float f1 = p.wx1 * hf.y + p.wx2 * hf2;
        float s1 = p.wy1 * Sb[r+1] + p.wy2 * Sb[r];
        float e1 = f1 - s1;
        acc += my * e1 * e1;
    }
    return acc;
}

__global__ __launch_bounds__(256, 6)
void loss_kernel(const float* __restrict__ grid,
                 const float* __restrict__ gt,
                 const float* __restrict__ gd,
                 const float* __restrict__ mask,
                 int B, unsigned int units, float* __restrict__ out)
{
    __shared__ float sh[9 * ROWP];
    __shared__ unsigned int s_u;
    __shared__ float wsum[8];
    const int tid = threadIdx.x;
    const int j0 = 2 * tid;

    if (tid == 0) s_u = atomicAdd(&g_work, 1u);

    float facc = 0.0f;

    for (;;) {
        __syncthreads();                       // prev compute done; s_u stable
        const unsigned int u = s_u;
        if (u >= units) break;

        const int b  = (int)(u >> 7);          // 128 strips per batch item
        const int i0 = (int)(u & 127u) * 4;

        const float dx = -8.0f * gt[2 * b + 0];
        const float dy =  8.0f * gt[2 * b + 1];

        Prm p;
        p.sx = gd[2 * b + 0];
        p.sy = gd[2 * b + 1];
        const float dx1f = floorf(dx), dy1f = floorf(dy);
        p.dx1 = (int)dx1f;  p.dy1 = (int)dy1f;  p.dy2 = p.dy1 + 1;
        p.wx1 = (dx1f + 1.0f) - dx;  p.wx2 = dx - dx1f;
        p.wy1 = (dy1f + 1.0f) - dy;  p.wy2 = dy - dy1f;
        p.w11 = p.wy1 * p.wx1;  p.w12 = p.wy1 * p.wx2;
        p.w21 = p.wy2 * p.wx1;  p.w22 = p.wy2 * p.wx2;
        p.g0 = grid + (size_t)(2 * b + 0) * HH * WW;
        p.g1 = grid + (size_t)(2 * b + 1) * HH * WW;
        p.mk = mask + (size_t)b * HH * WW;
        p.imax = HH - p.dy2;
        p.i0 = i0;  p.j0 = j0;

        float uacc, cnt;
        if (dx > 0.0f) {
            p.jmax = WW - (p.dx1 + 1);
            cnt = (float)p.imax * (float)p.jmax;
            // stage 5 shifted h-rows (src i0+dy1+t, row-clamped)
            #pragma unroll
            for (int t = 0; t < 5; t++) {
                const int src = min(i0 + p.dy1 + t, HH - 1) * WW;
                float2 a = ld2(p.g0 + src + j0);
                float2 g = ld2(p.g1 + src + j0);
                float2 h = make_float2(p.sy * a.x + p.sx * g.x,
                                       p.sy * a.y + p.sx * g.y);
                *(float2*)(sh + t * ROWP + j0) = h;
                if (tid == 255) {
                    #pragma unroll
                    for (int k = 0; k < 16; k++) sh[t * ROWP + 512 + k] = h.y;
                }
            }
            __syncthreads();
            if (tid == 0) s_u = atomicAdd(&g_work, 1u);   // prefetch next
            if (p.dx1 & 1) uacc = pos_compute<1>(p, sh);
            else           uacc = pos_compute<0>(p, sh);
        } else {
            p.jmax = WW + p.dx1;
            cnt = (float)p.imax * (float)p.jmax;
            // stage rows 0..4: h at src i0+t (second term)
            #pragma unroll
            for (int t = 0; t < 5; t++) {
                const int src = min(i0 + t, HH - 1) * WW;
                float2 a = ld2(p.g0 + src + j0);
                float2 g = ld2(p.g1 + src + j0);
                float2 h = make_float2(p.sy * a.x + p.sx * g.x,
                                       p.sy * a.y + p.sx * g.y);
                *(float2*)(sh + t * ROWP + j0) = h;
                if (tid == 255) {
                    #pragma unroll
                    for (int k = 0; k < 16; k++) sh[t * ROWP + 512 + k] = h.y;
                }
            }
            // stage rows 5..8: h at src i0+dy2+t (first term)
            #pragma unroll
            for (int t = 0; t < 4; t++) {
                const int src = min(i0 + p.dy2 + t, HH - 1) * WW;
                float2 a = ld2(p.g0 + src + j0);
                float2 g = ld2(p.g1 + src + j0);
                float2 h = make_float2(p.sy * a.x + p.sx * g.x,
                                       p.sy * a.y + p.sx * g.y);
                *(float2*)(sh + (5 + t) * ROWP + j0) = h;
                if (tid == 255) {
                    #pragma unroll
                    for (int k = 0; k < 16; k++) sh[(5 + t) * ROWP + 512 + k] = h.y;
                }
            }
            __syncthreads();
            if (tid == 0) s_u = atomicAdd(&g_work, 1u);   // prefetch next
            if ((-p.dx1) & 1) uacc = neg_compute<1>(p, sh);
            else              uacc = neg_compute<0>(p, sh);
        }
        facc += __fdividef(uacc, cnt);
    }

    // ---- block reduction (8 warps)
    #pragma unroll
    for (int o = 16; o > 0; o >>= 1)
        facc += __shfl_down_sync(0xFFFFFFFFu, facc, o);

    const int lane = tid & 31;
    const int warp = tid >> 5;
    if (lane == 0) wsum[warp] = facc;
    __syncthreads();

    if (tid == 0) {
        float s = 0.0f;
        #pragma unroll
        for (int k = 0; k < 8; k++) s += wsum[k];
        atomicAdd(&g_acc, (double)s);

        __threadfence();
        unsigned int prev = atomicInc(&g_ticket, (unsigned int)gridDim.x - 1u);
        if (prev == (unsigned int)gridDim.x - 1u) {
            double total = atomicAdd(&g_acc, 0.0);    // atomic read
            out[0] = (float)(total / (double)B);
            g_acc  = 0.0;                             // reset for next replay
            g_work = 0u;
            __threadfence();
        }
    }
}

extern "C" void kernel_launch(void* const* d_in, const int* in_sizes, int n_in,
                              void* d_out, int out_size)
{
    const float* grid = (const float*)d_in[0];
    const float* gt   = (const float*)d_in[1];
    const float* gd   = (const float*)d_in[2];
    const float* mask = (const float*)d_in[3];
    float* out = (float*)d_out;

    const int B = in_sizes[1] / 2;            // gt_sym_axis is (B, 2)
    const unsigned int units = (unsigned int)(128 * B);

    loss_kernel<<<NPERSIST, 256>>>(grid, gt, gd, mask, B, units, out);
}

// round 14
// speedup vs baseline: 1.8958x; 1.1885x over previous
#include <cuda_runtime.h>

// -------------------------------------------------------------------------
// MaskedBilinearFullSymLoss — B=16, C=2, H=W=512, scalar f32 output.
// Persistent single-wave kernel (888 blocks = 6/SM x 148), STATIC unit
// assignment (u = bid + k*gridDim.x) -> no intra-loop sync, warps fully
// independent (no load-burst convoy). Body = R11: float2 loads, parity-
// templated shifted windows, 4-row sharing, 8 px/thread.
// -------------------------------------------------------------------------

#define HH 512
#define WW 512
#define NPERSIST 888u

__device__ double g_acc;            // zero-initialized
__device__ unsigned int g_ticket;   // zero-initialized

__device__ __forceinline__ float2 ld2(const float* __restrict__ p) {
    return *(const float2*)p;
}

struct Ctx {
    const float* __restrict__ g0;
    const float* __restrict__ g1;
    const float* __restrict__ mk;
    float wx1, wx2, wy1, wy2, w11, w12, w21, w22, sym_x, sym_y;
    int dx1, dy1, dy2, imax, jmax, i0, j0;
};

// 3-float shifted window [ja, ja+1, ja+2]; P = ja parity. Clamped values are
// only consumed with a zero validity factor.
template<int P>
__device__ __forceinline__ void ldwin(const float* __restrict__ row, int ja,
                                      float& x0, float& x1, float& x2) {
    if (P == 0) {
        float2 v = ld2(row + min(ja, WW - 2));
        float  s = row[min(ja + 2, WW - 1)];
        x0 = v.x; x1 = v.y; x2 = s;
    } else {
        float2 a = ld2(row + min(ja - 1, WW - 2));
        float2 b = ld2(row + min(ja + 1, WW - 2));
        x0 = a.y; x1 = b.x; x2 = b.y;
    }
}

// 2-float window [c, c+1]; Q = c parity.
template<int Q>
__device__ __forceinline__ void ldpair(const float* __restrict__ row, int c,
                                       float& y0, float& y1) {
    if (Q == 0) {
        float2 v = ld2(row + min(c, WW - 2));
        y0 = v.x; y1 = v.y;
    } else {
        y0 = row[min(c,     WW - 1)];
        y1 = row[min(c + 1, WW - 1)];
    }
}

// ---- positive branch: output rows (ib, ib+1), cols (j0, j0+1)
template<int P>
__device__ __forceinline__ float pos_pair(const Ctx& c, int ib) {
    const int ja = c.j0 + c.dx1;
    int os[3];
    #pragma unroll
    for (int t = 0; t < 3; t++) os[t] = min(ib + c.dy1 + t, HH - 1) * WW;

    float X0[3], X1[3], X2[3];
    float Y0[3], Y1[3], Y2[3];
    #pragma unroll
    for (int t = 0; t < 3; t++) {
        ldwin<P>(c.g0 + os[t], ja, X0[t], X1[t], X2[t]);
        ldwin<P>(c.g1 + os[t], ja, Y0[t], Y1[t], Y2[t]);
    }

    const float jv0 = (c.j0     < c.jmax) ? 1.0f : 0.0f;
    const float jv1 = (c.j0 + 1 < c.jmax) ? 1.0f : 0.0f;

    float acc = 0.0f;
    #pragma unroll
    for (int r = 0; r < 2; r++) {
        const int oc = (ib + r) * WW + c.j0;     // always in-bounds
        float2 c0 = ld2(c.g0 + oc);
        float2 c1 = ld2(c.g1 + oc);
        float2 mm = ld2(c.mk + oc);
        const float rvv = (ib + r < c.imax) ? 1.0f : 0.0f;
        mm.x *= rvv * jv0;
        mm.y *= rvv * jv1;
        float s0 = c.w11 * X0[r] + c.w12 * X1[r] + c.w21 * X0[r+1] + c.w22 * X1[r+1];
        float s1 = c.w11 * Y0[r] + c.w12 * Y1[r] + c.w21 * Y0[r+1] + c.w22 * Y1[r+1];
        float e0 = (c0.x - s0) * c.sym_y + (c1.x - s1) * c.sym_x;
        acc += mm.x * e0 * e0;
        float t0 = c.w11 * X1[r] + c.w12 * X2[r] + c.w21 * X1[r+1] + c.w22 * X2[r+1];
        float t1 = c.w11 * Y1[r] + c.w12 * Y2[r] + c.w21 * Y1[r+1] + c.w22 * Y2[r+1];
        float e1 = (c0.y - t0) * c.sym_y + (c1.y - t1) * c.sym_x;
        acc += mm.y * e1 * e1;
    }
    return acc;
}

// ---- negative branch: rows (ib, ib+1), cols (j0, j0+1)
template<int Q>
__device__ __forceinline__ float neg_pair(const Ctx& c, int ib) {
    const int m2  = -c.dx1;            // >= 0
    const int cB0 = c.j0 + m2;

    float S0a[3], S0b[3], S1a[3], S1b[3];
    #pragma unroll
    for (int t = 0; t < 3; t++) {
        const int os = min(ib + t, HH - 1) * WW;
        ldpair<Q>(c.g0 + os, cB0, S0a[t], S0b[t]);
        ldpair<Q>(c.g1 + os, cB0, S1a[t], S1b[t]);
    }

    const float jv0 = (c.j0     < c.jmax) ? 1.0f : 0.0f;
    const float jv1 = (c.j0 + 1 < c.jmax) ? 1.0f : 0.0f;

    float acc = 0.0f;
    #pragma unroll
    for (int r = 0; r < 2; r++) {
        const int of = min(ib + c.dy2 + r, HH - 1) * WW;
        float2 v0 = ld2(c.g0 + of + c.j0);
        float2 v1 = ld2(c.g1 + of + c.j0);
        float z0 = c.g0[of + min(c.j0 + 2, WW - 1)];
        float z1 = c.g1[of + min(c.j0 + 2, WW - 1)];
        float mx, my;
        ldpair<Q>(c.mk + of, cB0, mx, my);
        const float rvv = (ib + r < c.imax) ? 1.0f : 0.0f;
        mx *= rvv * jv0;
        my *= rvv * jv1;
        float f0 = c.wx1 * v0.x + c.wx2 * v0.y;
        float f1 = c.wx1 * v1.x + c.wx2 * v1.y;
        float s0 = c.wy1 * S0a[r+1] + c.wy2 * S0a[r];
        float s1 = c.wy1 * S1a[r+1] + c.wy2 * S1a[r];
        float e0 = (f0 - s0) * c.sym_y + (f1 - s1) * c.sym_x;
        acc += mx * e0 * e0;
        float g0v = c.wx1 * v0.y + c.wx2 * z0;
        float g1v = c.wx1 * v1.y + c.wx2 * z1;
        float u0 = c.wy1 * S0b[r+1] + c.wy2 * S0b[r];
        float u1 = c.wy1 * S1b[r+1] + c.wy2 * S1b[r];
        float e1 = (g0v - u0) * c.sym_y + (g1v - u1) * c.sym_x;
        acc += my * e1 * e1;
    }
    return acc;
}

__global__ __launch_bounds__(256, 6)
void loss_kernel(const float* __restrict__ grid,
                 const float* __restrict__ gt,
                 const float* __restrict__ gd,
                 const float* __restrict__ mask,
                 int B, unsigned int units, float* __restrict__ out)
{
    const int H = HH, W = WW;
    const int tid = threadIdx.x;

    __shared__ float wsum[8];

    float facc = 0.0f;

    // static assignment; warps proceed fully independently (no shared state)
    for (unsigned int u = blockIdx.x; u < units; u += gridDim.x) {
        const int b  = (int)(u >> 7);         // 128 strips per batch item
        const int i0 = (int)(u & 127u) * 4;

        const float dx = -8.0f * gt[2 * b + 0];
        const float dy =  8.0f * gt[2 * b + 1];

        Ctx c;
        c.sym_x = gd[2 * b + 0];
        c.sym_y = gd[2 * b + 1];
        const float dx1f = floorf(dx), dy1f = floorf(dy);
        c.dx1 = (int)dx1f;  c.dy1 = (int)dy1f;  c.dy2 = c.dy1 + 1;
        const int dx2 = c.dx1 + 1;
        c.wx1 = (dx1f + 1.0f) - dx;  c.wx2 = dx - dx1f;
        c.wy1 = (dy1f + 1.0f) - dy;  c.wy2 = dy - dy1f;
        c.w11 = c.wy1 * c.wx1;  c.w12 = c.wy1 * c.wx2;
        c.w21 = c.wy2 * c.wx1;  c.w22 = c.wy2 * c.wx2;
        c.g0 = grid + (size_t)(2 * b + 0) * H * W;
        c.g1 = grid + (size_t)(2 * b + 1) * H * W;
        c.mk = mask + (size_t)b * H * W;
        c.imax = H - c.dy2;
        c.i0 = i0;
        c.j0 = 2 * tid;

        float uacc;
        float cnt;
        if (dx > 0.0f) {
            c.jmax = W - dx2;
            cnt = (float)c.imax * (float)c.jmax;
            if (c.dx1 & 1) uacc = pos_pair<1>(c, i0) + pos_pair<1>(c, i0 + 2);
            else           uacc = pos_pair<0>(c, i0) + pos_pair<0>(c, i0 + 2);
        } else {
            c.jmax = W + c.dx1;
            cnt = (float)c.imax * (float)c.jmax;
            if ((-c.dx1) & 1) uacc = neg_pair<1>(c, i0) + neg_pair<1>(c, i0 + 2);
            else              uacc = neg_pair<0>(c, i0) + neg_pair<0>(c, i0 + 2);
        }
        facc += __fdividef(uacc, cnt);
    }

    // ---- block reduction (8 warps)
    #pragma unroll
    for (int o = 16; o > 0; o >>= 1)
        facc += __shfl_down_sync(0xFFFFFFFFu, facc, o);

    const int lane = tid & 31;
    const int warp = tid >> 5;
    if (lane == 0) wsum[warp] = facc;
    __syncthreads();

    if (tid == 0) {
        float s = 0.0f;
        #pragma unroll
        for (int k = 0; k < 8; k++) s += wsum[k];
        atomicAdd(&g_acc, (double)s);

        __threadfence();
        unsigned int prev = atomicInc(&g_ticket, (unsigned int)gridDim.x - 1u);
        if (prev == (unsigned int)gridDim.x - 1u) {
            double total = atomicAdd(&g_acc, 0.0);    // atomic read
            out[0] = (float)(total / (double)B);
            g_acc  = 0.0;                             // reset for next replay
            __threadfence();
        }
    }
}

extern "C" void kernel_launch(void* const* d_in, const int* in_sizes, int n_in,
                              void* d_out, int out_size)
{
    const float* grid = (const float*)d_in[0];
    const float* gt   = (const float*)d_in[1];
    const float* gd   = (const float*)d_in[2];
    const float* mask = (const float*)d_in[3];
    float* out = (float*)d_out;

    const int B = in_sizes[1] / 2;            // gt_sym_axis is (B, 2)
    const unsigned int units = (unsigned int)(128 * B);

    loss_kernel<<<NPERSIST, 256>>>(grid, gt, gd, mask, B, units, out);
}